// round 2
// baseline (speedup 1.0000x reference)
#include <cuda_runtime.h>
#include <cstdint>
#include <cstddef>

// Neural-CDE forward. y0 = coeffs[:,0,:]@W_init+b_init; 127 RK4 steps of
// f(y)= (3x lipswish layers + linear) with H=256; project every state by Wd.
// Persistent: 128 CTAs x 128 threads, CTA owns 8 batch rows for all time.
// Activations ping-pong in SMEM as [dim][row] (stride 12 floats, 16B aligned).
// Inner GEMM uses packed fma.rn.f32x2 (row pairs packed straight from LDS.128).

#define T_N   128
#define IN_N  32
#define H_N   256
#define OUT_N 32
#define MC    8
#define BST   12
#define NTH   128

__device__ __forceinline__ unsigned long long fma2(unsigned long long a,
                                                   unsigned long long b,
                                                   unsigned long long c) {
    unsigned long long d;
    asm("fma.rn.f32x2 %0, %1, %2, %3;" : "=l"(d) : "l"(a), "l"(b), "l"(c));
    return d;
}
__device__ __forceinline__ unsigned long long dup2(float x) {
    unsigned long long d; unsigned int u = __float_as_uint(x);
    asm("mov.b64 %0, {%1, %2};" : "=l"(d) : "r"(u), "r"(u));
    return d;
}
__device__ __forceinline__ float2 unpk(unsigned long long v) {
    unsigned int a, b;
    asm("mov.b64 {%0, %1}, %2;" : "=r"(a), "=r"(b) : "l"(v));
    return make_float2(__uint_as_float(a), __uint_as_float(b));
}
__device__ __forceinline__ float lipswish(float x) {
    return 0.909f * x / (1.0f + __expf(-x));
}

// o[c*8+m] = bias_c + sum_k buf[k][m] * W[k][n0+c],  c in {0,1}, m in 0..7.
// W row-major [K][H_N]. buf is [dim][row] stride BST. Double-buffered W loads.
template <int K>
__device__ __forceinline__ void gemmT(const float* __restrict__ W,
                                      const float* __restrict__ buf,
                                      int n0, float bx, float by,
                                      float* __restrict__ o)
{
    unsigned long long ox[4], oy[4];
    {
        unsigned long long bxx = dup2(bx), byy = dup2(by);
#pragma unroll
        for (int p = 0; p < 4; p++) { ox[p] = bxx; oy[p] = byy; }
    }
    const float* Wp = W + n0;
    float2 wc[8], wn[8];
#pragma unroll
    for (int j = 0; j < 8; j++) wc[j] = *(const float2*)(Wp + j * H_N);

#pragma unroll 1
    for (int kb = 0; kb < K; kb += 8) {
        const int kn = (kb + 8) & (K - 1);   // last block wraps (dead reload, harmless)
#pragma unroll
        for (int j = 0; j < 8; j++) wn[j] = *(const float2*)(Wp + (kn + j) * H_N);
#pragma unroll
        for (int j = 0; j < 8; j++) {
            const float* hp = buf + (kb + j) * BST;      // 48B stride -> 16B aligned
            ulonglong2 ua = *(const ulonglong2*)(hp);    // rows (0,1),(2,3) packed
            ulonglong2 ub = *(const ulonglong2*)(hp + 4);// rows (4,5),(6,7) packed
            unsigned long long wxx = dup2(wc[j].x);
            unsigned long long wyy = dup2(wc[j].y);
            ox[0] = fma2(ua.x, wxx, ox[0]);  ox[1] = fma2(ua.y, wxx, ox[1]);
            ox[2] = fma2(ub.x, wxx, ox[2]);  ox[3] = fma2(ub.y, wxx, ox[3]);
            oy[0] = fma2(ua.x, wyy, oy[0]);  oy[1] = fma2(ua.y, wyy, oy[1]);
            oy[2] = fma2(ub.x, wyy, oy[2]);  oy[3] = fma2(ub.y, wyy, oy[3]);
        }
#pragma unroll
        for (int j = 0; j < 8; j++) wc[j] = wn[j];
    }
#pragma unroll
    for (int p = 0; p < 4; p++) {
        float2 a = unpk(ox[p]); o[2 * p]     = a.x; o[2 * p + 1]     = a.y;
        float2 b = unpk(oy[p]); o[8 + 2 * p] = b.x; o[8 + 2 * p + 1] = b.y;
    }
}

// Write this thread's 2 columns (16 values, idx c*8+m) into buf[dim][row].
__device__ __forceinline__ void store16(float* __restrict__ buf, int n0,
                                        const float* __restrict__ v)
{
    *(float4*)(buf +  n0      * BST)     = make_float4(v[0],  v[1],  v[2],  v[3]);
    *(float4*)(buf +  n0      * BST + 4) = make_float4(v[4],  v[5],  v[6],  v[7]);
    *(float4*)(buf + (n0 + 1) * BST)     = make_float4(v[8],  v[9],  v[10], v[11]);
    *(float4*)(buf + (n0 + 1) * BST + 4) = make_float4(v[12], v[13], v[14], v[15]);
}

// Vector field: 3 lipswish layers ping-pong A->B->A->B, final linear from B -> k regs.
__device__ __forceinline__ void f_eval(const float* __restrict__ Wf,
                                       const float* __restrict__ bfb,
                                       float* bufA, float* bufB,
                                       int n0, float* __restrict__ k)
{
    float o[16];
    float* in = bufA; float* ob = bufB;
#pragma unroll 1
    for (int l = 0; l < 3; l++) {
        float2 bb = *(const float2*)(bfb + l * H_N + n0);
        gemmT<H_N>(Wf + (size_t)l * H_N * H_N, in, n0, bb.x, bb.y, o);
#pragma unroll
        for (int i = 0; i < 16; i++) o[i] = lipswish(o[i]);
        store16(ob, n0, o);
        __syncthreads();
        float* t = in; in = ob; ob = t;
    }
    float2 bb = *(const float2*)(bfb + 3 * H_N + n0);
    gemmT<H_N>(Wf + (size_t)3 * H_N * H_N, in, n0, bb.x, bb.y, k);
}

// out[bbase+r, t, c0..c0+1] = bd + sum_k buf[k][r] * Wd[k][c0..c0+1]
__device__ __forceinline__ void project(const float* __restrict__ buf,
                                        const float* __restrict__ Wd,
                                        const float* __restrict__ bd,
                                        float* __restrict__ out,
                                        int bbase, int t, int tid)
{
    const int r  = tid >> 4;
    const int c0 = (tid & 15) << 1;
    float2 bv = *(const float2*)(bd + c0);
    float s0 = bv.x, s1 = bv.y;
#pragma unroll 8
    for (int kk = 0; kk < H_N; kk++) {
        float h   = buf[kk * BST + r];
        float2 w  = *(const float2*)(Wd + kk * OUT_N + c0);
        s0 = fmaf(h, w.x, s0);
        s1 = fmaf(h, w.y, s1);
    }
    *(float2*)(out + ((size_t)(bbase + r) * T_N + t) * OUT_N + c0) = make_float2(s0, s1);
}

__global__ void __launch_bounds__(NTH, 1)
cde_kernel(const float* __restrict__ coeffs, const float* __restrict__ times,
           const float* __restrict__ Wi,     const float* __restrict__ bi,
           const float* __restrict__ Wf,     const float* __restrict__ bfb,
           const float* __restrict__ Wd,     const float* __restrict__ bd,
           float* __restrict__ out)
{
    __shared__ float bufA[H_N * BST];
    __shared__ float bufB[H_N * BST];

    const int tid   = threadIdx.x;
    const int bbase = blockIdx.x * MC;
    const int n0    = tid * 2;

    // Stage coeffs[:,0,:] -> bufA[k][m]   (8 rows x 32 in-dims)
    {
        int m = tid >> 4, kk = (tid & 15) << 1;
        float2 cv = *(const float2*)(coeffs + (size_t)(bbase + m) * T_N * IN_N + kk);
        bufA[kk * BST + m]       = cv.x;
        bufA[(kk + 1) * BST + m] = cv.y;
    }
    __syncthreads();

    float y[16];
    {
        float2 bb = *(const float2*)(bi + n0);
        gemmT<IN_N>(Wi, bufA, n0, bb.x, bb.y, y);
    }
    __syncthreads();            // everyone done READING bufA before we overwrite it
    store16(bufA, n0, y);
    __syncthreads();
    project(bufA, Wd, bd, out, bbase, 0, tid);

    float k[16], acc[16], s[16];
#pragma unroll 1
    for (int t = 0; t < T_N - 1; t++) {
        const float dt = times[t + 1] - times[t];

        f_eval(Wf, bfb, bufA, bufB, n0, k);                       // k1
#pragma unroll
        for (int i = 0; i < 16; i++) { acc[i] = k[i]; s[i] = fmaf(0.5f * dt, k[i], y[i]); }
        store16(bufA, n0, s); __syncthreads();

        f_eval(Wf, bfb, bufA, bufB, n0, k);                       // k2
#pragma unroll
        for (int i = 0; i < 16; i++) { acc[i] = fmaf(2.f, k[i], acc[i]); s[i] = fmaf(0.5f * dt, k[i], y[i]); }
        store16(bufA, n0, s); __syncthreads();

        f_eval(Wf, bfb, bufA, bufB, n0, k);                       // k3
#pragma unroll
        for (int i = 0; i < 16; i++) { acc[i] = fmaf(2.f, k[i], acc[i]); s[i] = fmaf(dt, k[i], y[i]); }
        store16(bufA, n0, s); __syncthreads();

        f_eval(Wf, bfb, bufA, bufB, n0, k);                       // k4
#pragma unroll
        for (int i = 0; i < 16; i++) { acc[i] += k[i]; y[i] = fmaf(dt * (1.f / 6.f), acc[i], y[i]); }
        store16(bufA, n0, y); __syncthreads();

        project(bufA, Wd, bd, out, bbase, t + 1, tid);
    }
}

extern "C" void kernel_launch(void* const* d_in, const int* in_sizes, int n_in,
                              void* d_out, int out_size)
{
    const float* coeffs = (const float*)d_in[0];
    const float* times  = (const float*)d_in[1];
    const float* Wi     = (const float*)d_in[2];
    const float* bi     = (const float*)d_in[3];
    const float* Wf     = (const float*)d_in[4];
    const float* bf     = (const float*)d_in[5];
    const float* Wd     = (const float*)d_in[6];
    const float* bd     = (const float*)d_in[7];
    float* out = (float*)d_out;

    const int B    = in_sizes[0] / (T_N * IN_N);   // 1024
    const int grid = B / MC;                       // 128
    cde_kernel<<<grid, NTH>>>(coeffs, times, Wi, bi, Wf, bf, Wd, bd, out);
}

// round 3
// speedup vs baseline: 1.6255x; 1.6255x over previous
#include <cuda_runtime.h>
#include <cstdint>
#include <cstddef>

// Neural-CDE forward. Persistent: 128 CTAs x 256 threads; CTA owns 8 batch rows
// for the whole integration. Split-K: two 128-thread groups each compute half
// the K-reduction of every GEMM; group 1 deposits partials in SMEM, group 0
// combines + activates. 2 warps/SMSP hides LDS/L2 latency that bound R2.
// Inner GEMM: packed fma.rn.f32x2, weights prefetched 2 blocks (16 k-rows) deep.

#define T_N   128
#define IN_N  32
#define H_N   256
#define OUT_N 32
#define MC    8      // batch rows per CTA
#define BST   12     // activation buffer stride [dim][row]
#define NTH   256
#define RST   20     // reduction buffer stride (floats) -> conflict-free

__device__ __forceinline__ unsigned long long fma2(unsigned long long a,
                                                   unsigned long long b,
                                                   unsigned long long c) {
    unsigned long long d;
    asm("fma.rn.f32x2 %0, %1, %2, %3;" : "=l"(d) : "l"(a), "l"(b), "l"(c));
    return d;
}
__device__ __forceinline__ unsigned long long dup2(float x) {
    unsigned long long d; unsigned int u = __float_as_uint(x);
    asm("mov.b64 %0, {%1, %2};" : "=l"(d) : "r"(u), "r"(u));
    return d;
}
__device__ __forceinline__ float2 unpk(unsigned long long v) {
    unsigned int a, b;
    asm("mov.b64 {%0, %1}, %2;" : "=r"(a), "=r"(b) : "l"(v));
    return make_float2(__uint_as_float(a), __uint_as_float(b));
}
__device__ __forceinline__ float lipswish(float x) {
    return 0.909f * x / (1.0f + __expf(-x));
}

// Partial GEMM over k in [koff, koff+KS):
//   o[c*8+m] = bias_c + sum_k buf[k][m] * W[k][n0+c],  c in {0,1}, m in 0..7.
// W row-major [*][H_N]; buf [dim][row], stride BST. Distance-2 W prefetch.
template <int KS>
__device__ __forceinline__ void gemmT(const float* __restrict__ W,
                                      const float* __restrict__ buf,
                                      int n0, int koff, float bx, float by,
                                      float* __restrict__ o)
{
    unsigned long long ox[4], oy[4];
    {
        unsigned long long bxx = dup2(bx), byy = dup2(by);
#pragma unroll
        for (int p = 0; p < 4; p++) { ox[p] = bxx; oy[p] = byy; }
    }
    const float* Wp = W + (size_t)koff * H_N + n0;
    const float* bp = buf + koff * BST;

    float2 wA[8], wB[8];
#pragma unroll
    for (int j = 0; j < 8; j++) wA[j] = *(const float2*)(Wp + j * H_N);
#pragma unroll
    for (int j = 0; j < 8; j++) wB[j] = *(const float2*)(Wp + ((8 + j) & (KS - 1)) * H_N);

#pragma unroll 1
    for (int kb = 0; kb < KS; kb += 8) {
        const int kn = (kb + 16) & (KS - 1);   // wrap: dead reload on tail, harmless
        float2 wN[8];
#pragma unroll
        for (int j = 0; j < 8; j++) wN[j] = *(const float2*)(Wp + (kn + j) * H_N);
#pragma unroll
        for (int j = 0; j < 8; j++) {
            const float* hp = bp + (kb + j) * BST;        // 48B stride, 16B aligned
            ulonglong2 ua = *(const ulonglong2*)(hp);     // rows (0,1),(2,3)
            ulonglong2 ub = *(const ulonglong2*)(hp + 4); // rows (4,5),(6,7)
            unsigned long long wxx = dup2(wA[j].x);
            unsigned long long wyy = dup2(wA[j].y);
            ox[0] = fma2(ua.x, wxx, ox[0]);  ox[1] = fma2(ua.y, wxx, ox[1]);
            ox[2] = fma2(ub.x, wxx, ox[2]);  ox[3] = fma2(ub.y, wxx, ox[3]);
            oy[0] = fma2(ua.x, wyy, oy[0]);  oy[1] = fma2(ua.y, wyy, oy[1]);
            oy[2] = fma2(ub.x, wyy, oy[2]);  oy[3] = fma2(ub.y, wyy, oy[3]);
        }
#pragma unroll
        for (int j = 0; j < 8; j++) { wA[j] = wB[j]; wB[j] = wN[j]; }
    }
#pragma unroll
    for (int p = 0; p < 4; p++) {
        float2 a = unpk(ox[p]); o[2 * p]     = a.x; o[2 * p + 1]     = a.y;
        float2 b = unpk(oy[p]); o[8 + 2 * p] = b.x; o[8 + 2 * p + 1] = b.y;
    }
}

// Write this thread's 2 columns (16 values, idx c*8+m) into buf[dim][row].
__device__ __forceinline__ void store16(float* __restrict__ buf, int n0,
                                        const float* __restrict__ v)
{
    *(float4*)(buf +  n0      * BST)     = make_float4(v[0],  v[1],  v[2],  v[3]);
    *(float4*)(buf +  n0      * BST + 4) = make_float4(v[4],  v[5],  v[6],  v[7]);
    *(float4*)(buf + (n0 + 1) * BST)     = make_float4(v[8],  v[9],  v[10], v[11]);
    *(float4*)(buf + (n0 + 1) * BST + 4) = make_float4(v[12], v[13], v[14], v[15]);
}

// Group 1: deposit 16 partials. Group 0 (after barrier): combine into o.
__device__ __forceinline__ void red_put(float* __restrict__ red, int ct,
                                        const float* __restrict__ v)
{
    float* p = red + ct * RST;
    *(float4*)(p)      = make_float4(v[0],  v[1],  v[2],  v[3]);
    *(float4*)(p + 4)  = make_float4(v[4],  v[5],  v[6],  v[7]);
    *(float4*)(p + 8)  = make_float4(v[8],  v[9],  v[10], v[11]);
    *(float4*)(p + 12) = make_float4(v[12], v[13], v[14], v[15]);
}
__device__ __forceinline__ void red_add(const float* __restrict__ red, int ct,
                                        float* __restrict__ o)
{
    const float* p = red + ct * RST;
    float4 r0 = *(const float4*)(p);
    float4 r1 = *(const float4*)(p + 4);
    float4 r2 = *(const float4*)(p + 8);
    float4 r3 = *(const float4*)(p + 12);
    o[0] += r0.x; o[1] += r0.y; o[2]  += r0.z; o[3]  += r0.w;
    o[4] += r1.x; o[5] += r1.y; o[6]  += r1.z; o[7]  += r1.w;
    o[8] += r2.x; o[9] += r2.y; o[10] += r2.z; o[11] += r2.w;
    o[12]+= r3.x; o[13]+= r3.y; o[14] += r3.z; o[15] += r3.w;
}

// Vector field: 3 lipswish layers ping-pong A->B->A->B, final linear -> kreg (g0).
__device__ __forceinline__ void f_eval(const float* __restrict__ Wf,
                                       const float* __restrict__ bfb,
                                       float* bufA, float* bufB, float* red,
                                       int n0, int kg, int ct,
                                       float* __restrict__ kreg)
{
    float o[16];
    float* in = bufA; float* ob = bufB;
    const int koff = kg * (H_N / 2);
#pragma unroll 1
    for (int l = 0; l < 3; l++) {
        float bx = 0.f, by = 0.f;
        if (kg == 0) { float2 bb = *(const float2*)(bfb + l * H_N + n0); bx = bb.x; by = bb.y; }
        gemmT<H_N / 2>(Wf + (size_t)l * H_N * H_N, in, n0, koff, bx, by, o);
        if (kg == 1) red_put(red, ct, o);
        __syncthreads();
        if (kg == 0) {
            red_add(red, ct, o);
#pragma unroll
            for (int i = 0; i < 16; i++) o[i] = lipswish(o[i]);
            store16(ob, n0, o);
        }
        __syncthreads();
        float* t = in; in = ob; ob = t;
    }
    float bx = 0.f, by = 0.f;
    if (kg == 0) { float2 bb = *(const float2*)(bfb + 3 * H_N + n0); bx = bb.x; by = bb.y; }
    gemmT<H_N / 2>(Wf + (size_t)3 * H_N * H_N, in, n0, koff, bx, by, o);
    if (kg == 1) red_put(red, ct, o);
    __syncthreads();
    if (kg == 0) {
        red_add(red, ct, o);
#pragma unroll
        for (int i = 0; i < 16; i++) kreg[i] = o[i];
    }
}

// out[bbase+r, t, c] = bd[c] + sum_k buf[k][r] * Wd[k][c]; one thread per output.
__device__ __forceinline__ void project(const float* __restrict__ buf,
                                        const float* __restrict__ Wd,
                                        const float* __restrict__ bd,
                                        float* __restrict__ out,
                                        int bbase, int t, int tid)
{
    const int r = tid >> 5;
    const int c = tid & 31;
    float s = bd[c];
#pragma unroll 8
    for (int kk = 0; kk < H_N; kk++)
        s = fmaf(buf[kk * BST + r], Wd[kk * OUT_N + c], s);
    out[((size_t)(bbase + r) * T_N + t) * OUT_N + c] = s;
}

__global__ void __launch_bounds__(NTH, 1)
cde_kernel(const float* __restrict__ coeffs, const float* __restrict__ times,
           const float* __restrict__ Wi,     const float* __restrict__ bi,
           const float* __restrict__ Wf,     const float* __restrict__ bfb,
           const float* __restrict__ Wd,     const float* __restrict__ bd,
           float* __restrict__ out)
{
    __shared__ float bufA[H_N * BST];
    __shared__ float bufB[H_N * BST];
    __shared__ float red[128 * RST];

    const int tid   = threadIdx.x;
    const int kg    = tid >> 7;        // K-group: 0 or 1
    const int ct    = tid & 127;       // column-thread id within group
    const int n0    = ct * 2;
    const int bbase = blockIdx.x * MC;

    // Stage coeffs[:,0,:] -> bufA[k][m]  (8 rows x 32 in-dims, 1 value/thread)
    {
        int m = tid >> 5, kk = tid & 31;
        bufA[kk * BST + m] = coeffs[(size_t)(bbase + m) * T_N * IN_N + kk];
    }
    __syncthreads();

    float y[16];
    {
        float bx = 0.f, by = 0.f;
        if (kg == 0) { float2 bb = *(const float2*)(bi + n0); bx = bb.x; by = bb.y; }
        float o[16];
        gemmT<IN_N / 2>(Wi, bufA, n0, kg * (IN_N / 2), bx, by, o);
        if (kg == 1) red_put(red, ct, o);
        __syncthreads();
        if (kg == 0) {
            red_add(red, ct, o);
#pragma unroll
            for (int i = 0; i < 16; i++) y[i] = o[i];
            store16(bufA, n0, y);
        }
        __syncthreads();
    }
    project(bufA, Wd, bd, out, bbase, 0, tid);

    float k[16], acc[16];
#pragma unroll 1
    for (int t = 0; t < T_N - 1; t++) {
        const float dt = times[t + 1] - times[t];
        float s[16];

        f_eval(Wf, bfb, bufA, bufB, red, n0, kg, ct, k);          // k1
        if (kg == 0) {
#pragma unroll
            for (int i = 0; i < 16; i++) { acc[i] = k[i]; s[i] = fmaf(0.5f * dt, k[i], y[i]); }
            store16(bufA, n0, s);
        }
        __syncthreads();

        f_eval(Wf, bfb, bufA, bufB, red, n0, kg, ct, k);          // k2
        if (kg == 0) {
#pragma unroll
            for (int i = 0; i < 16; i++) { acc[i] = fmaf(2.f, k[i], acc[i]); s[i] = fmaf(0.5f * dt, k[i], y[i]); }
            store16(bufA, n0, s);
        }
        __syncthreads();

        f_eval(Wf, bfb, bufA, bufB, red, n0, kg, ct, k);          // k3
        if (kg == 0) {
#pragma unroll
            for (int i = 0; i < 16; i++) { acc[i] = fmaf(2.f, k[i], acc[i]); s[i] = fmaf(dt, k[i], y[i]); }
            store16(bufA, n0, s);
        }
        __syncthreads();

        f_eval(Wf, bfb, bufA, bufB, red, n0, kg, ct, k);          // k4
        if (kg == 0) {
#pragma unroll
            for (int i = 0; i < 16; i++) { acc[i] += k[i]; y[i] = fmaf(dt * (1.f / 6.f), acc[i], y[i]); }
            store16(bufA, n0, y);
        }
        __syncthreads();

        project(bufA, Wd, bd, out, bbase, t + 1, tid);
    }
}

extern "C" void kernel_launch(void* const* d_in, const int* in_sizes, int n_in,
                              void* d_out, int out_size)
{
    const float* coeffs = (const float*)d_in[0];
    const float* times  = (const float*)d_in[1];
    const float* Wi     = (const float*)d_in[2];
    const float* bi     = (const float*)d_in[3];
    const float* Wf     = (const float*)d_in[4];
    const float* bf     = (const float*)d_in[5];
    const float* Wd     = (const float*)d_in[6];
    const float* bd     = (const float*)d_in[7];
    float* out = (float*)d_out;

    const int B    = in_sizes[0] / (T_N * IN_N);   // 1024
    const int grid = B / MC;                       // 128
    cde_kernel<<<grid, NTH>>>(coeffs, times, Wi, bi, Wf, bf, Wd, bd, out);
}

// round 4
// speedup vs baseline: 1.6644x; 1.0239x over previous
#include <cuda_runtime.h>
#include <cstdint>
#include <cstddef>

// Neural-CDE forward, R4: 128 CTAs x 512 threads (4 warps/SMSP), 4-way split-K.
// All 4 groups compute raw K-partials of each GEMM and deposit to SMEM; the
// combine + lipswish + RK4 state update is DISTRIBUTED across all 512 threads
// (each owns 4 of the 2048 state elements -> y/acc live in 8 regs/thread).
// Inner GEMM: packed fma.rn.f32x2, distance-2 weight prefetch from L2.

#define T_N   128
#define IN_N  32
#define H_N   256
#define OUT_N 32
#define MC    8      // batch rows per CTA
#define BST   8      // activation buffer stride [dim][row] (broadcast reads)
#define NTH   512
#define NG    4      // split-K groups
#define KSH   (H_N / NG)   // 64
#define KSI   (IN_N / NG)  // 8

__device__ __forceinline__ unsigned long long fma2(unsigned long long a,
                                                   unsigned long long b,
                                                   unsigned long long c) {
    unsigned long long d;
    asm("fma.rn.f32x2 %0, %1, %2, %3;" : "=l"(d) : "l"(a), "l"(b), "l"(c));
    return d;
}
__device__ __forceinline__ unsigned long long dup2(float x) {
    unsigned long long d; unsigned int u = __float_as_uint(x);
    asm("mov.b64 %0, {%1, %2};" : "=l"(d) : "r"(u), "r"(u));
    return d;
}
__device__ __forceinline__ float2 unpk(unsigned long long v) {
    unsigned int a, b;
    asm("mov.b64 {%0, %1}, %2;" : "=r"(a), "=r"(b) : "l"(v));
    return make_float2(__uint_as_float(a), __uint_as_float(b));
}
__device__ __forceinline__ float lipswish(float x) {
    return 0.909f * x / (1.0f + __expf(-x));
}

// Raw partial GEMM over k in [koff, koff+KS):
//   o[c*8+m] = sum_k buf[k][m] * W[k][n0+c],  c in {0,1}, m in 0..7.
// W row-major [*][H_N]; buf [dim][row] stride BST. Distance-2 W prefetch.
template <int KS>
__device__ __forceinline__ void gemmT(const float* __restrict__ W,
                                      const float* __restrict__ buf,
                                      int n0, int koff,
                                      float* __restrict__ o)
{
    unsigned long long ox[4] = {0ull, 0ull, 0ull, 0ull};
    unsigned long long oy[4] = {0ull, 0ull, 0ull, 0ull};
    const float* Wp = W + (size_t)koff * H_N + n0;
    const float* bp = buf + koff * BST;

    float2 wA[8], wB[8];
#pragma unroll
    for (int j = 0; j < 8; j++) wA[j] = *(const float2*)(Wp + j * H_N);
#pragma unroll
    for (int j = 0; j < 8; j++) wB[j] = *(const float2*)(Wp + ((8 + j) & (KS - 1)) * H_N);

#pragma unroll 1
    for (int kb = 0; kb < KS; kb += 8) {
        const int kn = (kb + 16) & (KS - 1);   // wrap: dead reload on tail, harmless
        float2 wN[8];
#pragma unroll
        for (int j = 0; j < 8; j++) wN[j] = *(const float2*)(Wp + (kn + j) * H_N);
#pragma unroll
        for (int j = 0; j < 8; j++) {
            const float* hp = bp + (kb + j) * BST;        // 32B stride, 16B aligned
            ulonglong2 ua = *(const ulonglong2*)(hp);     // rows (0,1),(2,3)
            ulonglong2 ub = *(const ulonglong2*)(hp + 4); // rows (4,5),(6,7)
            unsigned long long wxx = dup2(wA[j].x);
            unsigned long long wyy = dup2(wA[j].y);
            ox[0] = fma2(ua.x, wxx, ox[0]);  ox[1] = fma2(ua.y, wxx, ox[1]);
            ox[2] = fma2(ub.x, wxx, ox[2]);  ox[3] = fma2(ub.y, wxx, ox[3]);
            oy[0] = fma2(ua.x, wyy, oy[0]);  oy[1] = fma2(ua.y, wyy, oy[1]);
            oy[2] = fma2(ub.x, wyy, oy[2]);  oy[3] = fma2(ub.y, wyy, oy[3]);
        }
#pragma unroll
        for (int j = 0; j < 8; j++) { wA[j] = wB[j]; wB[j] = wN[j]; }
    }
#pragma unroll
    for (int p = 0; p < 4; p++) {
        float2 a = unpk(ox[p]); o[2 * p]     = a.x; o[2 * p + 1]     = a.y;
        float2 b = unpk(oy[p]); o[8 + 2 * p] = b.x; o[8 + 2 * p + 1] = b.y;
    }
}

// Deposit 16 raw partials at red[(kg*128+ct)*16 .. +16).
__device__ __forceinline__ void red_put(float* __restrict__ rp,
                                        const float* __restrict__ v)
{
    *(float4*)(rp)      = make_float4(v[0],  v[1],  v[2],  v[3]);
    *(float4*)(rp + 4)  = make_float4(v[4],  v[5],  v[6],  v[7]);
    *(float4*)(rp + 8)  = make_float4(v[8],  v[9],  v[10], v[11]);
    *(float4*)(rp + 12) = make_float4(v[12], v[13], v[14], v[15]);
}

// Combine 4 group-partials for this thread's 4 elements (conflict-free LDS.128).
__device__ __forceinline__ float4 combine4(const float* __restrict__ red,
                                           int ct_e, int i0)
{
    const float* p0 = red + (0 * 128 + ct_e) * 16 + i0;
    const float* p1 = red + (1 * 128 + ct_e) * 16 + i0;
    const float* p2 = red + (2 * 128 + ct_e) * 16 + i0;
    const float* p3 = red + (3 * 128 + ct_e) * 16 + i0;
    float4 a = *(const float4*)p0;
    float4 b = *(const float4*)p1;
    float4 c = *(const float4*)p2;
    float4 d = *(const float4*)p3;
    return make_float4(a.x + b.x + c.x + d.x, a.y + b.y + c.y + d.y,
                       a.z + b.z + c.z + d.z, a.w + b.w + c.w + d.w);
}

__global__ void __launch_bounds__(NTH, 1)
cde_kernel(const float* __restrict__ coeffs, const float* __restrict__ times,
           const float* __restrict__ Wi,     const float* __restrict__ bi,
           const float* __restrict__ Wf,     const float* __restrict__ bfb,
           const float* __restrict__ Wd,     const float* __restrict__ bd,
           float* __restrict__ out)
{
    __shared__ float bufA[H_N * BST];          // 8 KB
    __shared__ float bufB[H_N * BST];          // 8 KB (also project scratch)
    __shared__ float red[NG * 128 * 16];       // 32 KB

    const int tid   = threadIdx.x;
    const int kg    = tid >> 7;                // split-K group 0..3
    const int ct    = tid & 127;               // column-thread in group
    const int n0    = ct * 2;
    const int koffH = kg * KSH;
    const int bbase = blockIdx.x * MC;

    // combine/update mapping: this thread owns state elems 4*tid .. 4*tid+3
    const int n_e  = tid >> 1;                 // column 0..255
    const int ct_e = tid >> 2;
    const int m0   = (tid & 1) * 4;            // row offset 0 or 4
    const int i0   = ((tid >> 1) & 1) * 8 + m0;

    float* redp = red + (kg * 128 + ct) * 16;
    float o[16];

    // ---- stage coeffs[:,0,:] -> bufA[k][m] ----
    if (tid < 256) {
        int m = tid >> 5, kk = tid & 31;
        bufA[kk * BST + m] = coeffs[(size_t)(bbase + m) * T_N * IN_N + kk];
    }
    __syncthreads();

    // ---- y0 = coeffs0 @ Wi + bi ----
    float y[4], acc[4];
    gemmT<KSI>(Wi, bufA, n0, kg * KSI, o);
    red_put(redp, o);
    __syncthreads();
    {
        float4 v = combine4(red, ct_e, i0);
        float bb = bi[n_e];
        y[0] = v.x + bb; y[1] = v.y + bb; y[2] = v.z + bb; y[3] = v.w + bb;
        *(float4*)(bufA + n_e * BST + m0) = make_float4(y[0], y[1], y[2], y[3]);
    }
    __syncthreads();

    // ---- project t=0 (K split in halves across the 512 threads) ----
    {
        const int out_id = tid & 255, kh = tid >> 8;
        const int r = out_id >> 5, c = out_id & 31;
        float s = (kh == 0) ? bd[c] : 0.f;
        const int k0 = kh * (H_N / 2);
#pragma unroll 8
        for (int kk = k0; kk < k0 + H_N / 2; kk++)
            s = fmaf(bufA[kk * BST + r], Wd[kk * OUT_N + c], s);
        if (kh) bufB[out_id] = s;
        __syncthreads();
        if (!kh)
            out[((size_t)(bbase + r) * T_N + 0) * OUT_N + c] = s + bufB[out_id];
    }

    // ---- time loop ----
#pragma unroll 1
    for (int t = 0; t < T_N - 1; t++) {
        const float dt = times[t + 1] - times[t];

#pragma unroll 1
        for (int st = 0; st < 4; st++) {
            float* in = bufA; float* ob = bufB;
            // 3 hidden lipswish layers
#pragma unroll 1
            for (int l = 0; l < 3; l++) {
                gemmT<KSH>(Wf + (size_t)l * H_N * H_N, in, n0, koffH, o);
                red_put(redp, o);
                __syncthreads();
                float4 v = combine4(red, ct_e, i0);
                float bb = bfb[l * H_N + n_e];
                v.x = lipswish(v.x + bb); v.y = lipswish(v.y + bb);
                v.z = lipswish(v.z + bb); v.w = lipswish(v.w + bb);
                *(float4*)(ob + n_e * BST + m0) = v;
                __syncthreads();
                float* tmp = in; in = ob; ob = tmp;
            }
            // final linear layer -> k
            gemmT<KSH>(Wf + (size_t)3 * H_N * H_N, in, n0, koffH, o);
            red_put(redp, o);
            __syncthreads();
            float4 kv = combine4(red, ct_e, i0);
            {
                float bb = bfb[3 * H_N + n_e];
                kv.x += bb; kv.y += bb; kv.z += bb; kv.w += bb;
            }
            float k4[4] = {kv.x, kv.y, kv.z, kv.w};
            float s4[4];
            if (st == 0) {
#pragma unroll
                for (int i = 0; i < 4; i++) { acc[i] = k4[i]; s4[i] = fmaf(0.5f * dt, k4[i], y[i]); }
            } else if (st == 1) {
#pragma unroll
                for (int i = 0; i < 4; i++) { acc[i] = fmaf(2.f, k4[i], acc[i]); s4[i] = fmaf(0.5f * dt, k4[i], y[i]); }
            } else if (st == 2) {
#pragma unroll
                for (int i = 0; i < 4; i++) { acc[i] = fmaf(2.f, k4[i], acc[i]); s4[i] = fmaf(dt, k4[i], y[i]); }
            } else {
#pragma unroll
                for (int i = 0; i < 4; i++) { acc[i] += k4[i]; y[i] = fmaf(dt * (1.f / 6.f), acc[i], y[i]); s4[i] = y[i]; }
            }
            *(float4*)(bufA + n_e * BST + m0) = make_float4(s4[0], s4[1], s4[2], s4[3]);
            __syncthreads();
        }

        // ---- project t+1 from bufA (= y_{t+1}); bufB[0..256) is dead scratch ----
        {
            const int out_id = tid & 255, kh = tid >> 8;
            const int r = out_id >> 5, c = out_id & 31;
            float s = (kh == 0) ? bd[c] : 0.f;
            const int k0 = kh * (H_N / 2);
#pragma unroll 8
            for (int kk = k0; kk < k0 + H_N / 2; kk++)
                s = fmaf(bufA[kk * BST + r], Wd[kk * OUT_N + c], s);
            if (kh) bufB[out_id] = s;
            __syncthreads();
            if (!kh)
                out[((size_t)(bbase + r) * T_N + (t + 1)) * OUT_N + c] = s + bufB[out_id];
        }
    }
}

extern "C" void kernel_launch(void* const* d_in, const int* in_sizes, int n_in,
                              void* d_out, int out_size)
{
    const float* coeffs = (const float*)d_in[0];
    const float* times  = (const float*)d_in[1];
    const float* Wi     = (const float*)d_in[2];
    const float* bi     = (const float*)d_in[3];
    const float* Wf     = (const float*)d_in[4];
    const float* bf     = (const float*)d_in[5];
    const float* Wd     = (const float*)d_in[6];
    const float* bd     = (const float*)d_in[7];
    float* out = (float*)d_out;

    const int B    = in_sizes[0] / (T_N * IN_N);   // 1024
    const int grid = B / MC;                       // 128
    cde_kernel<<<grid, NTH>>>(coeffs, times, Wi, bi, Wf, bf, Wd, bd, out);
}

// round 5
// speedup vs baseline: 1.9487x; 1.1708x over previous
#include <cuda_runtime.h>
#include <cstdint>
#include <cstddef>

// Neural-CDE forward, R5: 128 CTAs x 512 threads; 8-way split-K, 4 weight
// columns per thread (halves LDS per FLOP vs R4 -> unblocks the saturated L1
// pipe). Raw packed f32x2 partials are deposited straight to a padded SMEM
// reduction buffer (stride 36 words: conflict-free STS.128/LDS.128); the
// combine + bias + lipswish + RK4 update is distributed over all 512 threads.

#define T_N   128
#define IN_N  32
#define H_N   256
#define OUT_N 32
#define MC    8            // batch rows per CTA
#define BST   8            // activation buffer stride [dim][row]
#define NTH   512
#define NG    8            // split-K groups
#define NCT   64           // column-threads per group (4 cols each)
#define KSH   (H_N / NG)   // 32
#define KSI   (IN_N / NG)  // 4
#define RST   36           // reduction stride in floats (32 data + 4 pad)

#define BUF_FLOATS   (H_N * BST)            // 2048
#define RED_FLOATS   (NG * NCT * RST)       // 18432
#define SMEM_FLOATS  (2 * BUF_FLOATS + RED_FLOATS)
#define SMEM_BYTES   (SMEM_FLOATS * 4)      // 90112

typedef unsigned long long u64;

__device__ __forceinline__ u64 fma2(u64 a, u64 b, u64 c) {
    u64 d;
    asm("fma.rn.f32x2 %0, %1, %2, %3;" : "=l"(d) : "l"(a), "l"(b), "l"(c));
    return d;
}
__device__ __forceinline__ u64 dup2(float x) {
    u64 d; unsigned int u = __float_as_uint(x);
    asm("mov.b64 %0, {%1, %2};" : "=l"(d) : "r"(u), "r"(u));
    return d;
}
__device__ __forceinline__ float lipswish(float x) {
    return 0.909f * x / (1.0f + __expf(-x));
}

// Raw partial GEMM over k in [koff, koff+KS), 4 columns n0..n0+3, 8 rows.
// acc[c*4+p] packs rows (2p,2p+1) of column n0+c.  W row-major [*][H_N];
// buf [dim][row] stride BST (broadcast reads).  Distance-2 weight prefetch
// in 4-k-row blocks (window ~2x190cyc > L2 262cyc).
template <int KS>
__device__ __forceinline__ void gemmT4(const float* __restrict__ W,
                                       const float* __restrict__ buf,
                                       int n0, int koff,
                                       u64* __restrict__ acc)
{
#pragma unroll
    for (int i = 0; i < 16; i++) acc[i] = 0ull;
    const float* Wp = W + (size_t)koff * H_N + n0;
    const float* bp = buf + koff * BST;

    float4 wA[4], wB[4];
#pragma unroll
    for (int j = 0; j < 4; j++) wA[j] = *(const float4*)(Wp + j * H_N);
#pragma unroll
    for (int j = 0; j < 4; j++) wB[j] = *(const float4*)(Wp + ((4 + j) & (KS - 1)) * H_N);

#pragma unroll 1
    for (int kb = 0; kb < KS; kb += 4) {
        const int kn = (kb + 8) & (KS - 1);     // wrap: dead reload on tail
        float4 wN[4];
#pragma unroll
        for (int j = 0; j < 4; j++) wN[j] = *(const float4*)(Wp + (kn + j) * H_N);
#pragma unroll
        for (int j = 0; j < 4; j++) {
            const float* hp = bp + (kb + j) * BST;
            ulonglong2 ua = *(const ulonglong2*)(hp);      // rows (0,1),(2,3)
            ulonglong2 ub = *(const ulonglong2*)(hp + 4);  // rows (4,5),(6,7)
            u64 w0 = dup2(wA[j].x), w1 = dup2(wA[j].y);
            u64 w2 = dup2(wA[j].z), w3 = dup2(wA[j].w);
            acc[0]  = fma2(ua.x, w0, acc[0]);  acc[1]  = fma2(ua.y, w0, acc[1]);
            acc[2]  = fma2(ub.x, w0, acc[2]);  acc[3]  = fma2(ub.y, w0, acc[3]);
            acc[4]  = fma2(ua.x, w1, acc[4]);  acc[5]  = fma2(ua.y, w1, acc[5]);
            acc[6]  = fma2(ub.x, w1, acc[6]);  acc[7]  = fma2(ub.y, w1, acc[7]);
            acc[8]  = fma2(ua.x, w2, acc[8]);  acc[9]  = fma2(ua.y, w2, acc[9]);
            acc[10] = fma2(ub.x, w2, acc[10]); acc[11] = fma2(ub.y, w2, acc[11]);
            acc[12] = fma2(ua.x, w3, acc[12]); acc[13] = fma2(ua.y, w3, acc[13]);
            acc[14] = fma2(ub.x, w3, acc[14]); acc[15] = fma2(ub.y, w3, acc[15]);
        }
#pragma unroll
        for (int j = 0; j < 4; j++) { wA[j] = wB[j]; wB[j] = wN[j]; }
    }
}

// Deposit 32 raw floats (16 packed pairs) at redp: layout word c*8+m.
__device__ __forceinline__ void red_put(float* __restrict__ redp,
                                        const u64* __restrict__ acc)
{
#pragma unroll
    for (int c = 0; c < 4; c++) {
        *(ulonglong2*)(redp + c * 8)     = make_ulonglong2(acc[c * 4],     acc[c * 4 + 1]);
        *(ulonglong2*)(redp + c * 8 + 4) = make_ulonglong2(acc[c * 4 + 2], acc[c * 4 + 3]);
    }
}

// Sum the 8 group-partials for this thread's float4 (conflict-free LDS.128).
__device__ __forceinline__ float4 combine8(const float* __restrict__ red,
                                           int ct_e, int off)
{
    const float* p = red + ct_e * RST + off;
    float4 s = *(const float4*)(p);
#pragma unroll
    for (int g = 1; g < NG; g++) {
        float4 v = *(const float4*)(p + g * NCT * RST);
        s.x += v.x; s.y += v.y; s.z += v.z; s.w += v.w;
    }
    return s;
}

__global__ void __launch_bounds__(NTH, 1)
cde_kernel(const float* __restrict__ coeffs, const float* __restrict__ times,
           const float* __restrict__ Wi,     const float* __restrict__ bi,
           const float* __restrict__ Wf,     const float* __restrict__ bfb,
           const float* __restrict__ Wd,     const float* __restrict__ bd,
           float* __restrict__ out)
{
    extern __shared__ float smem[];
    float* bufA = smem;                    // 2048 floats
    float* bufB = smem + BUF_FLOATS;       // 2048 floats (also project scratch)
    float* red  = smem + 2 * BUF_FLOATS;   // 18432 floats

    const int tid   = threadIdx.x;
    const int kg    = tid >> 6;                 // split-K group 0..7
    const int ct    = tid & 63;                 // column-thread in group
    const int n0    = ct * 4;
    const int bbase = blockIdx.x * MC;

    // combine/update mapping: thread owns column n_e, rows m0..m0+3
    const int ct_e = tid >> 3;
    const int sub  = tid & 7;
    const int c_e  = sub >> 1;
    const int m0   = (sub & 1) * 4;
    const int n_e  = ct_e * 4 + c_e;
    const int off  = c_e * 8 + m0;

    float* redp = red + (kg * NCT + ct) * RST;
    u64 acc[16];

    // ---- stage coeffs[:,0,:] -> bufA[k][m] ----
    if (tid < 256) {
        int m = tid >> 5, kk = tid & 31;
        bufA[kk * BST + m] = coeffs[(size_t)(bbase + m) * T_N * IN_N + kk];
    }
    __syncthreads();

    // ---- y0 = coeffs0 @ Wi + bi ----
    float y[4], ksum[4];
    gemmT4<KSI>(Wi, bufA, n0, kg * KSI, acc);
    red_put(redp, acc);
    __syncthreads();
    {
        float4 v = combine8(red, ct_e, off);
        float bb = bi[n_e];
        y[0] = v.x + bb; y[1] = v.y + bb; y[2] = v.z + bb; y[3] = v.w + bb;
        *(float4*)(bufA + n_e * BST + m0) = make_float4(y[0], y[1], y[2], y[3]);
    }
    __syncthreads();

    // ---- project t=0 (K split in halves across the 512 threads) ----
    {
        const int out_id = tid & 255, kh = tid >> 8;
        const int r = out_id >> 5, c = out_id & 31;
        float s = (kh == 0) ? bd[c] : 0.f;
        const int k0 = kh * (H_N / 2);
#pragma unroll 8
        for (int kk = k0; kk < k0 + H_N / 2; kk++)
            s = fmaf(bufA[kk * BST + r], Wd[kk * OUT_N + c], s);
        if (kh) bufB[out_id] = s;
        __syncthreads();
        if (!kh)
            out[((size_t)(bbase + r) * T_N + 0) * OUT_N + c] = s + bufB[out_id];
    }

    // ---- time loop ----
#pragma unroll 1
    for (int t = 0; t < T_N - 1; t++) {
        const float dt = times[t + 1] - times[t];

#pragma unroll 1
        for (int st = 0; st < 4; st++) {
            float* in = bufA; float* ob = bufB;
#pragma unroll 1
            for (int l = 0; l < 3; l++) {
                gemmT4<KSH>(Wf + (size_t)l * H_N * H_N, in, n0, kg * KSH, acc);
                red_put(redp, acc);
                __syncthreads();
                float4 v = combine8(red, ct_e, off);
                float bb = bfb[l * H_N + n_e];
                v.x = lipswish(v.x + bb); v.y = lipswish(v.y + bb);
                v.z = lipswish(v.z + bb); v.w = lipswish(v.w + bb);
                *(float4*)(ob + n_e * BST + m0) = v;
                __syncthreads();
                float* tmp = in; in = ob; ob = tmp;
            }
            gemmT4<KSH>(Wf + (size_t)3 * H_N * H_N, in, n0, kg * KSH, acc);
            red_put(redp, acc);
            __syncthreads();
            float4 kv = combine8(red, ct_e, off);
            {
                float bb = bfb[3 * H_N + n_e];
                kv.x += bb; kv.y += bb; kv.z += bb; kv.w += bb;
            }
            float k4[4] = {kv.x, kv.y, kv.z, kv.w};
            float s4[4];
            if (st == 0) {
#pragma unroll
                for (int i = 0; i < 4; i++) { ksum[i] = k4[i]; s4[i] = fmaf(0.5f * dt, k4[i], y[i]); }
            } else if (st == 1) {
#pragma unroll
                for (int i = 0; i < 4; i++) { ksum[i] = fmaf(2.f, k4[i], ksum[i]); s4[i] = fmaf(0.5f * dt, k4[i], y[i]); }
            } else if (st == 2) {
#pragma unroll
                for (int i = 0; i < 4; i++) { ksum[i] = fmaf(2.f, k4[i], ksum[i]); s4[i] = fmaf(dt, k4[i], y[i]); }
            } else {
#pragma unroll
                for (int i = 0; i < 4; i++) { ksum[i] += k4[i]; y[i] = fmaf(dt * (1.f / 6.f), ksum[i], y[i]); s4[i] = y[i]; }
            }
            *(float4*)(bufA + n_e * BST + m0) = make_float4(s4[0], s4[1], s4[2], s4[3]);
            __syncthreads();
        }

        // ---- project t+1 from bufA; bufB[0..256) is dead scratch here ----
        {
            const int out_id = tid & 255, kh = tid >> 8;
            const int r = out_id >> 5, c = out_id & 31;
            float s = (kh == 0) ? bd[c] : 0.f;
            const int k0 = kh * (H_N / 2);
#pragma unroll 8
            for (int kk = k0; kk < k0 + H_N / 2; kk++)
                s = fmaf(bufA[kk * BST + r], Wd[kk * OUT_N + c], s);
            if (kh) bufB[out_id] = s;
            __syncthreads();
            if (!kh)
                out[((size_t)(bbase + r) * T_N + (t + 1)) * OUT_N + c] = s + bufB[out_id];
        }
    }
}

extern "C" void kernel_launch(void* const* d_in, const int* in_sizes, int n_in,
                              void* d_out, int out_size)
{
    const float* coeffs = (const float*)d_in[0];
    const float* times  = (const float*)d_in[1];
    const float* Wi     = (const float*)d_in[2];
    const float* bi     = (const float*)d_in[3];
    const float* Wf     = (const float*)d_in[4];
    const float* bf     = (const float*)d_in[5];
    const float* Wd     = (const float*)d_in[6];
    const float* bd     = (const float*)d_in[7];
    float* out = (float*)d_out;

    cudaFuncSetAttribute(cde_kernel,
                         cudaFuncAttributeMaxDynamicSharedMemorySize, SMEM_BYTES);

    const int B    = in_sizes[0] / (T_N * IN_N);   // 1024
    const int grid = B / MC;                       // 128
    cde_kernel<<<grid, NTH, SMEM_BYTES>>>(coeffs, times, Wi, bi, Wf, bf, Wd, bd, out);
}

// round 6
// speedup vs baseline: 2.1878x; 1.1227x over previous
#include <cuda_runtime.h>
#include <cstdint>
#include <cstddef>

// Neural-CDE forward, R6: 128 CTAs x 512 threads; 8-way split-K, 4 cols/thread.
// vs R5: (1) GEMM k-loop fully unrolled -> immediate LDS/LDG offsets (kills
// ALU IMADs); (2) activation LDS software-pipelined one k-row ahead (hides
// 29cyc LDS latency under the FMA block); (3) projection folded into
// stage-0/layer-0, sharing the reduction barrier (removes the serial proj
// phase + 2 barriers per step).

#define T_N   128
#define IN_N  32
#define H_N   256
#define OUT_N 32
#define MC    8            // batch rows per CTA
#define BST   8            // activation buffer stride [dim][row]
#define NTH   512
#define NG    8            // split-K groups
#define NCT   64           // column-threads per group (4 cols each)
#define KSH   (H_N / NG)   // 32
#define KSI   (IN_N / NG)  // 4
#define RST   36           // reduction stride in floats (32 data + 4 pad)

#define BUF_FLOATS   (H_N * BST)            // 2048
#define RED_FLOATS   (NG * NCT * RST)       // 18432
#define SCR_FLOATS   256                    // projection partial scratch
#define SMEM_FLOATS  (2 * BUF_FLOATS + RED_FLOATS + SCR_FLOATS)
#define SMEM_BYTES   (SMEM_FLOATS * 4)      // 91136

typedef unsigned long long u64;

__device__ __forceinline__ u64 fma2(u64 a, u64 b, u64 c) {
    u64 d;
    asm("fma.rn.f32x2 %0, %1, %2, %3;" : "=l"(d) : "l"(a), "l"(b), "l"(c));
    return d;
}
__device__ __forceinline__ u64 dup2(float x) {
    u64 d; unsigned int u = __float_as_uint(x);
    asm("mov.b64 %0, {%1, %2};" : "=l"(d) : "r"(u), "r"(u));
    return d;
}
__device__ __forceinline__ float lipswish(float x) {
    return 0.909f * x / (1.0f + __expf(-x));
}

// Raw partial GEMM over k in [koff, koff+KS), 4 columns n0..n0+3, 8 rows.
// acc[c*4+p] packs rows (2p,2p+1) of column n0+c. Fully unrolled; activation
// LDS pipelined one k-row ahead; weights prefetched 2 blocks (8 k-rows) deep.
template <int KS>
__device__ __forceinline__ void gemmT4(const float* __restrict__ W,
                                       const float* __restrict__ buf,
                                       int n0, int koff,
                                       u64* __restrict__ acc)
{
#pragma unroll
    for (int i = 0; i < 16; i++) acc[i] = 0ull;
    const float* Wp = W + (size_t)koff * H_N + n0;
    const float* bp = buf + koff * BST;

    float4 wA[4], wB[4];
#pragma unroll
    for (int j = 0; j < 4; j++) wA[j] = *(const float4*)(Wp + j * H_N);
#pragma unroll
    for (int j = 0; j < 4; j++) wB[j] = *(const float4*)(Wp + ((4 + j) & (KS - 1)) * H_N);

    ulonglong2 ua = *(const ulonglong2*)(bp);       // k-row 0: rows (0,1),(2,3)
    ulonglong2 ub = *(const ulonglong2*)(bp + 4);   //          rows (4,5),(6,7)

#pragma unroll
    for (int kb = 0; kb < KS; kb += 4) {
        const int kn = (kb + 8) & (KS - 1);         // wrap: dead reload on tail
        float4 wN[4];
#pragma unroll
        for (int j = 0; j < 4; j++) wN[j] = *(const float4*)(Wp + (kn + j) * H_N);
#pragma unroll
        for (int j = 0; j < 4; j++) {
            const int knext = (kb + j + 1) & (KS - 1);        // pipelined act load
            ulonglong2 na = *(const ulonglong2*)(bp + knext * BST);
            ulonglong2 nb = *(const ulonglong2*)(bp + knext * BST + 4);
            u64 w0 = dup2(wA[j].x), w1 = dup2(wA[j].y);
            u64 w2 = dup2(wA[j].z), w3 = dup2(wA[j].w);
            acc[0]  = fma2(ua.x, w0, acc[0]);  acc[1]  = fma2(ua.y, w0, acc[1]);
            acc[2]  = fma2(ub.x, w0, acc[2]);  acc[3]  = fma2(ub.y, w0, acc[3]);
            acc[4]  = fma2(ua.x, w1, acc[4]);  acc[5]  = fma2(ua.y, w1, acc[5]);
            acc[6]  = fma2(ub.x, w1, acc[6]);  acc[7]  = fma2(ub.y, w1, acc[7]);
            acc[8]  = fma2(ua.x, w2, acc[8]);  acc[9]  = fma2(ua.y, w2, acc[9]);
            acc[10] = fma2(ub.x, w2, acc[10]); acc[11] = fma2(ub.y, w2, acc[11]);
            acc[12] = fma2(ua.x, w3, acc[12]); acc[13] = fma2(ua.y, w3, acc[13]);
            acc[14] = fma2(ub.x, w3, acc[14]); acc[15] = fma2(ub.y, w3, acc[15]);
            ua = na; ub = nb;
        }
#pragma unroll
        for (int j = 0; j < 4; j++) { wA[j] = wB[j]; wB[j] = wN[j]; }
    }
}

// Deposit 32 raw floats (16 packed pairs) at redp: layout word c*8+m.
__device__ __forceinline__ void red_put(float* __restrict__ redp,
                                        const u64* __restrict__ acc)
{
#pragma unroll
    for (int c = 0; c < 4; c++) {
        *(ulonglong2*)(redp + c * 8)     = make_ulonglong2(acc[c * 4],     acc[c * 4 + 1]);
        *(ulonglong2*)(redp + c * 8 + 4) = make_ulonglong2(acc[c * 4 + 2], acc[c * 4 + 3]);
    }
}

// Sum the 8 group-partials for this thread's float4 (conflict-free LDS.128).
__device__ __forceinline__ float4 combine8(const float* __restrict__ red,
                                           int ct_e, int off)
{
    const float* p = red + ct_e * RST + off;
    float4 s = *(const float4*)(p);
#pragma unroll
    for (int g = 1; g < NG; g++) {
        float4 v = *(const float4*)(p + g * NCT * RST);
        s.x += v.x; s.y += v.y; s.z += v.z; s.w += v.w;
    }
    return s;
}

// Projection partial: s = [bd[c] +] sum_{k in half} buf[k][r] * Wd[k][c].
__device__ __forceinline__ float proj_part(const float* __restrict__ buf,
                                           const float* __restrict__ Wd,
                                           const float* __restrict__ bd,
                                           int kh, int r, int c)
{
    float s = (kh == 0) ? bd[c] : 0.f;
    const int k0 = kh * (H_N / 2);
#pragma unroll 8
    for (int kk = k0; kk < k0 + H_N / 2; kk++)
        s = fmaf(buf[kk * BST + r], Wd[kk * OUT_N + c], s);
    return s;
}

__global__ void __launch_bounds__(NTH, 1)
cde_kernel(const float* __restrict__ coeffs, const float* __restrict__ times,
           const float* __restrict__ Wi,     const float* __restrict__ bi,
           const float* __restrict__ Wf,     const float* __restrict__ bfb,
           const float* __restrict__ Wd,     const float* __restrict__ bd,
           float* __restrict__ out)
{
    extern __shared__ float smem[];
    float* bufA = smem;                                  // 2048 floats
    float* bufB = smem + BUF_FLOATS;                     // 2048 floats
    float* red  = smem + 2 * BUF_FLOATS;                 // 18432 floats
    float* scr  = smem + 2 * BUF_FLOATS + RED_FLOATS;    // 256 floats

    const int tid   = threadIdx.x;
    const int kg    = tid >> 6;                 // split-K group 0..7
    const int ct    = tid & 63;                 // column-thread in group
    const int n0    = ct * 4;
    const int bbase = blockIdx.x * MC;

    // combine/update mapping: thread owns column n_e, rows m0..m0+3
    const int ct_e = tid >> 3;
    const int sub  = tid & 7;
    const int c_e  = sub >> 1;
    const int m0   = (sub & 1) * 4;
    const int n_e  = ct_e * 4 + c_e;
    const int off  = c_e * 8 + m0;

    // projection mapping
    const int p_id = tid & 255;                 // output element 0..255
    const int p_kh = tid >> 8;                  // K-half 0/1
    const int p_r  = p_id >> 5;                 // batch row in CTA
    const int p_c  = p_id & 31;                 // output column

    float* redp = red + (kg * NCT + ct) * RST;
    u64 acc[16];

    // ---- stage coeffs[:,0,:] -> bufA[k][m] ----
    if (tid < 256) {
        int m = tid >> 5, kk = tid & 31;
        bufA[kk * BST + m] = coeffs[(size_t)(bbase + m) * T_N * IN_N + kk];
    }
    __syncthreads();

    // ---- y0 = coeffs0 @ Wi + bi ----
    float y[4], ksum[4];
    gemmT4<KSI>(Wi, bufA, n0, kg * KSI, acc);
    red_put(redp, acc);
    __syncthreads();
    {
        float4 v = combine8(red, ct_e, off);
        float bb = bi[n_e];
        y[0] = v.x + bb; y[1] = v.y + bb; y[2] = v.z + bb; y[3] = v.w + bb;
        *(float4*)(bufA + n_e * BST + m0) = make_float4(y[0], y[1], y[2], y[3]);
    }
    __syncthreads();

    // ---- time loop; proj of y_t is folded into stage-0/layer-0 of step t ----
#pragma unroll 1
    for (int t = 0; t < T_N - 1; t++) {
        const float dt = times[t + 1] - times[t];

#pragma unroll 1
        for (int st = 0; st < 4; st++) {
            float* in = bufA; float* ob = bufB;
            float ps = 0.f;
#pragma unroll 1
            for (int l = 0; l < 3; l++) {
                if (st == 0 && l == 0) {
                    // projection partial of y_t (bufA stable through this GEMM)
                    ps = proj_part(bufA, Wd, bd, p_kh, p_r, p_c);
                    if (p_kh) scr[p_id] = ps;
                }
                gemmT4<KSH>(Wf + (size_t)l * H_N * H_N, in, n0, kg * KSH, acc);
                red_put(redp, acc);
                __syncthreads();     // covers red partials (+ scr on st0/l0)
                if (st == 0 && l == 0 && !p_kh)
                    out[((size_t)(bbase + p_r) * T_N + t) * OUT_N + p_c] = ps + scr[p_id];
                float4 v = combine8(red, ct_e, off);
                float bb = bfb[l * H_N + n_e];
                v.x = lipswish(v.x + bb); v.y = lipswish(v.y + bb);
                v.z = lipswish(v.z + bb); v.w = lipswish(v.w + bb);
                *(float4*)(ob + n_e * BST + m0) = v;
                __syncthreads();
                float* tmp = in; in = ob; ob = tmp;
            }
            gemmT4<KSH>(Wf + (size_t)3 * H_N * H_N, in, n0, kg * KSH, acc);
            red_put(redp, acc);
            __syncthreads();
            float4 kv = combine8(red, ct_e, off);
            {
                float bb = bfb[3 * H_N + n_e];
                kv.x += bb; kv.y += bb; kv.z += bb; kv.w += bb;
            }
            float k4[4] = {kv.x, kv.y, kv.z, kv.w};
            float s4[4];
            if (st == 0) {
#pragma unroll
                for (int i = 0; i < 4; i++) { ksum[i] = k4[i]; s4[i] = fmaf(0.5f * dt, k4[i], y[i]); }
            } else if (st == 1) {
#pragma unroll
                for (int i = 0; i < 4; i++) { ksum[i] = fmaf(2.f, k4[i], ksum[i]); s4[i] = fmaf(0.5f * dt, k4[i], y[i]); }
            } else if (st == 2) {
#pragma unroll
                for (int i = 0; i < 4; i++) { ksum[i] = fmaf(2.f, k4[i], ksum[i]); s4[i] = fmaf(dt, k4[i], y[i]); }
            } else {
#pragma unroll
                for (int i = 0; i < 4; i++) { ksum[i] += k4[i]; y[i] = fmaf(dt * (1.f / 6.f), ksum[i], y[i]); s4[i] = y[i]; }
            }
            *(float4*)(bufA + n_e * BST + m0) = make_float4(s4[0], s4[1], s4[2], s4[3]);
            __syncthreads();
        }
    }

    // ---- final projection of y_{T-1} ----
    {
        float ps = proj_part(bufA, Wd, bd, p_kh, p_r, p_c);
        if (p_kh) scr[p_id] = ps;
        __syncthreads();
        if (!p_kh)
            out[((size_t)(bbase + p_r) * T_N + (T_N - 1)) * OUT_N + p_c] = ps + scr[p_id];
    }
}

extern "C" void kernel_launch(void* const* d_in, const int* in_sizes, int n_in,
                              void* d_out, int out_size)
{
    const float* coeffs = (const float*)d_in[0];
    const float* times  = (const float*)d_in[1];
    const float* Wi     = (const float*)d_in[2];
    const float* bi     = (const float*)d_in[3];
    const float* Wf     = (const float*)d_in[4];
    const float* bf     = (const float*)d_in[5];
    const float* Wd     = (const float*)d_in[6];
    const float* bd     = (const float*)d_in[7];
    float* out = (float*)d_out;

    cudaFuncSetAttribute(cde_kernel,
                         cudaFuncAttributeMaxDynamicSharedMemorySize, SMEM_BYTES);

    const int B    = in_sizes[0] / (T_N * IN_N);   // 1024
    const int grid = B / MC;                       // 128
    cde_kernel<<<grid, NTH, SMEM_BYTES>>>(coeffs, times, Wi, bi, Wf, bf, Wd, bd, out);
}